// round 13
// baseline (speedup 1.0000x reference)
#include <cuda_runtime.h>
#include <cuda_bf16.h>

#define NN   50000
#define EMB  128
#define HC   192      // HEADS*HID = 3*64
#define NE   800000

#define GEMM_BX 391                    // ceil(50000/128)
#define HIST_BLOCKS ((NE + 255) / 256)

// ---------------- scratch (device globals; no allocation allowed) ----------
__device__ float g_xl[(size_t)NN * HC];
__device__ float g_xr[(size_t)NN * HC];
__device__ int   g_cnt[NN];
__device__ int   g_off[NN];
__device__ int2  g_edge[NE];
__device__ float g_scores[NN];

// ---------------- bf16 split helpers ----------------------------------------
__device__ __forceinline__ void split2(float x, float y, unsigned& h, unsigned& l) {
    __nv_bfloat162 hh = __floats2bfloat162_rn(x, y);
    float hx = __bfloat162float(hh.x), hy = __bfloat162float(hh.y);
    __nv_bfloat162 ll = __floats2bfloat162_rn(x - hx, y - hy);
    h = *reinterpret_cast<unsigned*>(&hh);
    l = *reinterpret_cast<unsigned*>(&ll);
}

#define MMA_BF16(d, a0, a1, a2, a3, b0, b1)                                    \
    asm volatile(                                                              \
        "mma.sync.aligned.m16n8k16.row.col.f32.bf16.bf16.f32 "                 \
        "{%0,%1,%2,%3}, {%4,%5,%6,%7}, {%8,%9}, {%0,%1,%2,%3};"                \
        : "+f"(d[0]), "+f"(d[1]), "+f"(d[2]), "+f"(d[3])                       \
        : "r"(a0), "r"(a1), "r"(a2), "r"(a3), "r"(b0), "r"(b1))

// ---------------- bf16-split HMMA GEMM (proven R10) --------------------------
#define PITCH 72
#define OFF_AH 0
#define OFF_AL (128 * PITCH * 2)
#define OFF_WH (2 * 128 * PITCH * 2)
#define OFF_WL (2 * 128 * PITCH * 2 + 192 * PITCH * 2)
#define SM_TOT (2 * 128 * PITCH * 2 + 2 * 192 * PITCH * 2)   // 92160 B

__global__ void __launch_bounds__(256) k_gemm_mma(
    const float* __restrict__ A,
    const float* __restrict__ Wl, const float* __restrict__ bl,
    const float* __restrict__ Wr, const float* __restrict__ br)
{
    extern __shared__ char sm[];
    __nv_bfloat16* AH = (__nv_bfloat16*)(sm + OFF_AH);
    __nv_bfloat16* AL = (__nv_bfloat16*)(sm + OFF_AL);
    __nv_bfloat16* WH = (__nv_bfloat16*)(sm + OFF_WH);
    __nv_bfloat16* WL = (__nv_bfloat16*)(sm + OFF_WL);

    int bz = blockIdx.y;
    const float* W    = bz ? Wr : Wl;
    const float* bias = bz ? br : bl;
    float*       out  = bz ? g_xr : g_xl;
    int row0 = blockIdx.x * 128;

    int tid  = threadIdx.x;
    int w    = tid >> 5;
    int lane = tid & 31;
    int g    = lane >> 2;
    int t    = lane & 3;
    int mw   = (w & 1) * 64;
    int nw   = (w >> 1) * 48;

    float acc[4][6][4];
    #pragma unroll
    for (int mf = 0; mf < 4; mf++)
        #pragma unroll
        for (int nf = 0; nf < 6; nf++)
            #pragma unroll
            for (int q = 0; q < 4; q++) acc[mf][nf][q] = 0.f;

    for (int kc = 0; kc < 2; kc++) {
        int k0f4 = kc * 16;
        __syncthreads();

        #pragma unroll
        for (int it = 0; it < 8; it++) {
            int idx = it * 256 + tid;
            int row = idx >> 4;
            int fq  = idx & 15;
            int gr  = row0 + row;
            if (gr >= NN) gr = NN - 1;
            float4 v = ((const float4*)A)[(size_t)gr * 32 + k0f4 + fq];
            unsigned h01, l01, h23, l23;
            split2(v.x, v.y, h01, l01);
            split2(v.z, v.w, h23, l23);
            int e = row * PITCH + fq * 4;
            *(uint2*)&AH[e] = make_uint2(h01, h23);
            *(uint2*)&AL[e] = make_uint2(l01, l23);
        }
        #pragma unroll
        for (int it = 0; it < 12; it++) {
            int idx = it * 256 + tid;
            int row = idx >> 4;
            int fq  = idx & 15;
            float4 v = ((const float4*)W)[(size_t)row * 32 + k0f4 + fq];
            unsigned h01, l01, h23, l23;
            split2(v.x, v.y, h01, l01);
            split2(v.z, v.w, h23, l23);
            int e = row * PITCH + fq * 4;
            *(uint2*)&WH[e] = make_uint2(h01, h23);
            *(uint2*)&WL[e] = make_uint2(l01, l23);
        }
        __syncthreads();

        #pragma unroll
        for (int ks = 0; ks < 4; ks++) {
            int kk = ks * 16;
            unsigned ah[4][4], al[4][4], bh[6][2], blo[6][2];
            #pragma unroll
            for (int mf = 0; mf < 4; mf++) {
                int r = mw + mf * 16 + g;
                int e0 = r * PITCH + kk + 2 * t;
                int e1 = (r + 8) * PITCH + kk + 2 * t;
                ah[mf][0] = *(const unsigned*)&AH[e0];
                ah[mf][1] = *(const unsigned*)&AH[e1];
                ah[mf][2] = *(const unsigned*)&AH[e0 + 8];
                ah[mf][3] = *(const unsigned*)&AH[e1 + 8];
                al[mf][0] = *(const unsigned*)&AL[e0];
                al[mf][1] = *(const unsigned*)&AL[e1];
                al[mf][2] = *(const unsigned*)&AL[e0 + 8];
                al[mf][3] = *(const unsigned*)&AL[e1 + 8];
            }
            #pragma unroll
            for (int nf = 0; nf < 6; nf++) {
                int c = nw + nf * 8 + g;
                int e = c * PITCH + kk + 2 * t;
                bh[nf][0]  = *(const unsigned*)&WH[e];
                bh[nf][1]  = *(const unsigned*)&WH[e + 8];
                blo[nf][0] = *(const unsigned*)&WL[e];
                blo[nf][1] = *(const unsigned*)&WL[e + 8];
            }
            #pragma unroll
            for (int mf = 0; mf < 4; mf++)
                #pragma unroll
                for (int nf = 0; nf < 6; nf++) {
                    MMA_BF16(acc[mf][nf], ah[mf][0], ah[mf][1], ah[mf][2], ah[mf][3],
                             bh[nf][0], bh[nf][1]);
                    MMA_BF16(acc[mf][nf], ah[mf][0], ah[mf][1], ah[mf][2], ah[mf][3],
                             blo[nf][0], blo[nf][1]);
                    MMA_BF16(acc[mf][nf], al[mf][0], al[mf][1], al[mf][2], al[mf][3],
                             bh[nf][0], bh[nf][1]);
                }
        }
    }

    #pragma unroll
    for (int mf = 0; mf < 4; mf++) {
        int r0 = row0 + mw + mf * 16 + g;
        #pragma unroll
        for (int nf = 0; nf < 6; nf++) {
            int col = nw + nf * 8 + 2 * t;
            float b0 = __ldg(&bias[col]), b1 = __ldg(&bias[col + 1]);
            float* d = acc[mf][nf];
            if (r0 < NN)
                *(float2*)&out[(size_t)r0 * HC + col] = make_float2(d[0] + b0, d[1] + b1);
            if (r0 + 8 < NN)
                *(float2*)&out[(size_t)(r0 + 8) * HC + col] = make_float2(d[2] + b0, d[3] + b1);
        }
    }
}

// ---------------- histogram -------------------------------------------------
__global__ void k_hist(const int* __restrict__ ei) {
    int e = blockIdx.x * blockDim.x + threadIdx.x;
    if (e < NE) atomicAdd(&g_cnt[ei[NE + e]], 1);
}

// ---------------- x4-vectorized exclusive scan (single block) --------------
__global__ void k_scan() {
    __shared__ int wsum[32];
    __shared__ int carry;
    int tid  = threadIdx.x;
    int lane = tid & 31;
    int wid  = tid >> 5;
    if (tid == 0) carry = 0;
    __syncthreads();

    for (int base = 0; base < NN; base += 4096) {
        int idx = base + tid * 4;
        int4 v = make_int4(0, 0, 0, 0);
        if (idx < NN) v = *(const int4*)&g_cnt[idx];
        int t0 = v.x;
        int t1 = t0 + v.y;
        int t2 = t1 + v.z;
        int t3 = t2 + v.w;
        int x = t3;
        #pragma unroll
        for (int o = 1; o < 32; o <<= 1) {
            int t = __shfl_up_sync(0xffffffffu, x, o);
            if (lane >= o) x += t;
        }
        if (lane == 31) wsum[wid] = x;
        __syncthreads();
        if (wid == 0) {
            int s = wsum[lane];
            #pragma unroll
            for (int o = 1; o < 32; o <<= 1) {
                int t = __shfl_up_sync(0xffffffffu, s, o);
                if (lane >= o) s += t;
            }
            wsum[lane] = s;
        }
        __syncthreads();
        int c = carry;
        int b = (wid > 0 ? wsum[wid - 1] : 0) + c + x - t3;
        if (idx < NN)
            *(int4*)&g_off[idx] = make_int4(b, b + t0, b + t1, b + t2);
        __syncthreads();
        if (tid == 0) carry = c + wsum[31];
        __syncthreads();
    }
}

// ---------------- scatter ----------------------------------------------------
__global__ void k_scatter(const int* __restrict__ ei, const float* __restrict__ ea) {
    int e = blockIdx.x * blockDim.x + threadIdx.x;
    if (e >= NE) return;
    int s = ei[e];
    int d = ei[NE + e];
    int p = atomicAdd(&g_off[d], 1);
    g_edge[p] = make_int2(s, __float_as_int(ea[e]));
}

// ---------------- node-per-CTA aggregation: depth-2 gather pipeline ---------
// 32-thread blocks (one node each -> no block-retirement tail).
// lane (grp=l>>4, p=l&15) holds channels 64h + 4p..4p+3 per head h.
// gathers issued 2 iterations ahead, edge recs 3 ahead: no intra-iteration
// load->load dependence and a full iteration of slack on the gather.
__global__ void __launch_bounds__(32) k_agg(
    const float* __restrict__ We, const float* __restrict__ att,
    const float* __restrict__ bias, const float* __restrict__ Wout,
    const float* __restrict__ bout)
{
    int n = blockIdx.x;
    int l = threadIdx.x;
    int grp = l >> 4, p = l & 15;

    int end = g_off[n];
    int beg = (n > 0) ? g_off[n - 1] : 0;

    const float LOG2E = 1.44269504088896f;
    float4 xi[3], av[3], wv[3];
    {
        const float* xrp = &g_xr[(size_t)n * HC + 4 * p];
        #pragma unroll
        for (int h = 0; h < 3; h++) {
            xi[h] = *(const float4*)(xrp + 64 * h);
            float4 a = *(const float4*)&att[64 * h + 4 * p];
            av[h] = make_float4(a.x * LOG2E, a.y * LOG2E, a.z * LOG2E, a.w * LOG2E);
            wv[h] = *(const float4*)&We[64 * h + 4 * p];
        }
    }

    float  rsum[3] = {0.f, 0.f, 0.f};
    float4 acc[3]  = {{0,0,0,0}, {0,0,0,0}, {0,0,0,0}};

    if (end > beg) {
        int i0  = beg + grp;
        int lim = end - 1;
        int iA = (i0     < end) ? i0     : lim;
        int iB = (i0 + 2 < end) ? i0 + 2 : lim;
        int iC = (i0 + 4 < end) ? i0 + 4 : lim;
        int2 edA = g_edge[iA];
        int2 edB = g_edge[iB];
        int2 edC = g_edge[iC];
        float4 xa0, xa1, xa2, xb0, xb1, xb2;
        {
            const float* bp = &g_xl[(size_t)edA.x * HC + 4 * p];
            xa0 = *(const float4*)(bp);
            xa1 = *(const float4*)(bp + 64);
            xa2 = *(const float4*)(bp + 128);
        }
        {
            const float* bp = &g_xl[(size_t)edB.x * HC + 4 * p];
            xb0 = *(const float4*)(bp);
            xb1 = *(const float4*)(bp + 64);
            xb2 = *(const float4*)(bp + 128);
        }

        int niter = (end - beg + 1) >> 1;       // group-0 count (max)
        for (int it = 0; it < niter; it++) {
            int i = i0 + 2 * it;
            // fetch edge rec 3 ahead (no consumer this iteration)
            int iD = (i + 6 < end) ? i + 6 : lim;
            int2 edD = g_edge[iD];
            // gather xj 2 ahead (address edC.x known since last iteration)
            float4 xc0, xc1, xc2;
            {
                const float* bp = &g_xl[(size_t)edC.x * HC + 4 * p];
                xc0 = *(const float4*)(bp);
                xc1 = *(const float4*)(bp + 64);
                xc2 = *(const float4*)(bp + 128);
            }

            float fe = __int_as_float(edA.y);
            float s0, s1, s2;
            {
                float mx, my, mz, mw_, sm, sa;
                // head 0
                mx  = fmaf(fe, wv[0].x, xi[0].x) + xa0.x;
                my  = fmaf(fe, wv[0].y, xi[0].y) + xa0.y;
                mz  = fmaf(fe, wv[0].z, xi[0].z) + xa0.z;
                mw_ = fmaf(fe, wv[0].w, xi[0].w) + xa0.w;
                sm = av[0].x * mx;               sa = av[0].x * fabsf(mx);
                sm = fmaf(av[0].y, my,  sm);     sa = fmaf(av[0].y, fabsf(my),  sa);
                sm = fmaf(av[0].z, mz,  sm);     sa = fmaf(av[0].z, fabsf(mz),  sa);
                sm = fmaf(av[0].w, mw_, sm);     sa = fmaf(av[0].w, fabsf(mw_), sa);
                s0 = fmaf(0.6f, sm, 0.4f * sa);
                // head 1
                mx  = fmaf(fe, wv[1].x, xi[1].x) + xa1.x;
                my  = fmaf(fe, wv[1].y, xi[1].y) + xa1.y;
                mz  = fmaf(fe, wv[1].z, xi[1].z) + xa1.z;
                mw_ = fmaf(fe, wv[1].w, xi[1].w) + xa1.w;
                sm = av[1].x * mx;               sa = av[1].x * fabsf(mx);
                sm = fmaf(av[1].y, my,  sm);     sa = fmaf(av[1].y, fabsf(my),  sa);
                sm = fmaf(av[1].z, mz,  sm);     sa = fmaf(av[1].z, fabsf(mz),  sa);
                sm = fmaf(av[1].w, mw_, sm);     sa = fmaf(av[1].w, fabsf(mw_), sa);
                s1 = fmaf(0.6f, sm, 0.4f * sa);
                // head 2
                mx  = fmaf(fe, wv[2].x, xi[2].x) + xa2.x;
                my  = fmaf(fe, wv[2].y, xi[2].y) + xa2.y;
                mz  = fmaf(fe, wv[2].z, xi[2].z) + xa2.z;
                mw_ = fmaf(fe, wv[2].w, xi[2].w) + xa2.w;
                sm = av[2].x * mx;               sa = av[2].x * fabsf(mx);
                sm = fmaf(av[2].y, my,  sm);     sa = fmaf(av[2].y, fabsf(my),  sa);
                sm = fmaf(av[2].z, mz,  sm);     sa = fmaf(av[2].z, fabsf(mz),  sa);
                sm = fmaf(av[2].w, mw_, sm);     sa = fmaf(av[2].w, fabsf(mw_), sa);
                s2 = fmaf(0.6f, sm, 0.4f * sa);
            }
            // 16-lane (within-group) reduction
            #pragma unroll
            for (int o = 8; o > 0; o >>= 1) {
                s0 += __shfl_xor_sync(0xffffffffu, s0, o);
                s1 += __shfl_xor_sync(0xffffffffu, s1, o);
                s2 += __shfl_xor_sync(0xffffffffu, s2, o);
            }
            bool valid = (i < end);
            float w0 = valid ? exp2f(s0) : 0.f;
            float w1 = valid ? exp2f(s1) : 0.f;
            float w2 = valid ? exp2f(s2) : 0.f;
            rsum[0] += w0; rsum[1] += w1; rsum[2] += w2;
            acc[0].x = fmaf(w0, xa0.x, acc[0].x); acc[0].y = fmaf(w0, xa0.y, acc[0].y);
            acc[0].z = fmaf(w0, xa0.z, acc[0].z); acc[0].w = fmaf(w0, xa0.w, acc[0].w);
            acc[1].x = fmaf(w1, xa1.x, acc[1].x); acc[1].y = fmaf(w1, xa1.y, acc[1].y);
            acc[1].z = fmaf(w1, xa1.z, acc[1].z); acc[1].w = fmaf(w1, xa1.w, acc[1].w);
            acc[2].x = fmaf(w2, xa2.x, acc[2].x); acc[2].y = fmaf(w2, xa2.y, acc[2].y);
            acc[2].z = fmaf(w2, xa2.z, acc[2].z); acc[2].w = fmaf(w2, xa2.w, acc[2].w);

            // rotate pipeline
            edA = edB; edB = edC; edC = edD;
            xa0 = xb0; xa1 = xb1; xa2 = xb2;
            xb0 = xc0; xb1 = xc1; xb2 = xc2;
        }

        // combine the two groups (same channels at l and l^16)
        #pragma unroll
        for (int h = 0; h < 3; h++) {
            rsum[h] += __shfl_xor_sync(0xffffffffu, rsum[h], 16);
            acc[h].x += __shfl_xor_sync(0xffffffffu, acc[h].x, 16);
            acc[h].y += __shfl_xor_sync(0xffffffffu, acc[h].y, 16);
            acc[h].z += __shfl_xor_sync(0xffffffffu, acc[h].z, 16);
            acc[h].w += __shfl_xor_sync(0xffffffffu, acc[h].w, 16);
        }
    }

    float4 o = make_float4(0.f, 0.f, 0.f, 0.f);
    if (end > beg) {
        float r0 = 1.f / rsum[0], r1 = 1.f / rsum[1], r2 = 1.f / rsum[2];
        o.x = (acc[0].x * r0 + acc[1].x * r1 + acc[2].x * r2) * (1.f / 3.f);
        o.y = (acc[0].y * r0 + acc[1].y * r1 + acc[2].y * r2) * (1.f / 3.f);
        o.z = (acc[0].z * r0 + acc[1].z * r1 + acc[2].z * r2) * (1.f / 3.f);
        o.w = (acc[0].w * r0 + acc[1].w * r1 + acc[2].w * r2) * (1.f / 3.f);
    }
    float4 bia = *(const float4*)&bias[4 * p];
    float4 wo  = *(const float4*)&Wout[4 * p];
    o.x += bia.x; o.y += bia.y; o.z += bia.z; o.w += bia.w;

    float sp = o.x * wo.x + o.y * wo.y + o.z * wo.z + o.w * wo.w;
    #pragma unroll
    for (int off = 8; off > 0; off >>= 1)
        sp += __shfl_xor_sync(0xffffffffu, sp, off);
    if (l == 0) g_scores[n] = sp + bout[0];
}

// ---------------- global softmax over 50k scores ---------------------------
__global__ void k_softmax(float* __restrict__ out) {
    __shared__ float redm[32];
    __shared__ float reds[32];
    int tid = threadIdx.x;

    float mx = -1e30f;
    for (int i = tid; i < NN; i += 1024) mx = fmaxf(mx, g_scores[i]);
    #pragma unroll
    for (int o = 16; o > 0; o >>= 1) mx = fmaxf(mx, __shfl_xor_sync(0xffffffffu, mx, o));
    if ((tid & 31) == 0) redm[tid >> 5] = mx;
    __syncthreads();
    if (tid < 32) {
        float v = redm[tid];
        #pragma unroll
        for (int o = 16; o > 0; o >>= 1) v = fmaxf(v, __shfl_xor_sync(0xffffffffu, v, o));
        redm[tid] = v;
    }
    __syncthreads();
    mx = redm[0];

    float sm = 0.f;
    for (int i = tid; i < NN; i += 1024) {
        float e = __expf(g_scores[i] - mx);
        out[i] = e;
        sm += e;
    }
    #pragma unroll
    for (int o = 16; o > 0; o >>= 1) sm += __shfl_xor_sync(0xffffffffu, sm, o);
    if ((tid & 31) == 0) reds[tid >> 5] = sm;
    __syncthreads();
    if (tid < 32) {
        float v = reds[tid];
        #pragma unroll
        for (int o = 16; o > 0; o >>= 1) v += __shfl_xor_sync(0xffffffffu, v, o);
        reds[tid] = v;
    }
    __syncthreads();
    float inv = 1.f / reds[0];

    for (int i = tid; i < NN; i += 1024) out[i] *= inv;
}

// ---------------- launch: fork CSR-build chain || HMMA GEMM ----------------
extern "C" void kernel_launch(void* const* d_in, const int* in_sizes, int n_in,
                              void* d_out, int out_size)
{
    const int*   ei   = (const int*)  d_in[0];
    const float* ea   = (const float*)d_in[1];
    const float* pe   = (const float*)d_in[2];
    // d_in[3] = sim_w: softmax over one element == 1.0 -> unused
    const float* Wl   = (const float*)d_in[4];
    const float* bl   = (const float*)d_in[5];
    const float* Wr   = (const float*)d_in[6];
    const float* br   = (const float*)d_in[7];
    const float* We   = (const float*)d_in[8];
    const float* att  = (const float*)d_in[9];
    const float* bgn  = (const float*)d_in[10];
    const float* Wout = (const float*)d_in[11];
    const float* bout = (const float*)d_in[12];
    float* out = (float*)d_out;

    static cudaStream_t s1 = nullptr;
    static cudaEvent_t evr = nullptr, evg = nullptr;
    if (s1 == nullptr) {
        cudaStreamCreateWithFlags(&s1, cudaStreamNonBlocking);
        cudaEventCreateWithFlags(&evr, cudaEventDisableTiming);
        cudaEventCreateWithFlags(&evg, cudaEventDisableTiming);
        cudaFuncSetAttribute(k_gemm_mma, cudaFuncAttributeMaxDynamicSharedMemorySize, SM_TOT);
    }

    void* p_cnt = nullptr;
    cudaGetSymbolAddress(&p_cnt, g_cnt);

    // fork: GEMM on s1, CSR build on default stream
    cudaEventRecord(evr, 0);
    cudaStreamWaitEvent(s1, evr, 0);
    k_gemm_mma<<<dim3(GEMM_BX, 2), 256, SM_TOT, s1>>>(pe, Wl, bl, Wr, br);
    cudaEventRecord(evg, s1);

    cudaMemsetAsync(p_cnt, 0, NN * sizeof(int), 0);
    k_hist<<<HIST_BLOCKS, 256>>>(ei);
    k_scan<<<1, 1024>>>();
    k_scatter<<<HIST_BLOCKS, 256>>>(ei, ea);

    // join: aggregation needs both xl/xr and the CSR
    cudaStreamWaitEvent(0, evg, 0);
    k_agg<<<NN, 32>>>(We, att, bgn, Wout, bout);
    k_softmax<<<1, 1024>>>(out);
}

// round 14
// speedup vs baseline: 1.0420x; 1.0420x over previous
#include <cuda_runtime.h>
#include <cuda_bf16.h>
#include <cuda_fp16.h>

#define NN   50000
#define EMB  128
#define HC   192      // HEADS*HID = 3*64
#define NE   800000

#define GEMM_BX 391                    // ceil(50000/128)
#define HIST_BLOCKS ((NE + 255) / 256)

// ---------------- scratch (device globals; no allocation allowed) ----------
__device__ __half g_xlh[(size_t)NN * HC];   // xl in fp16 (gather-side)
__device__ float  g_xr[(size_t)NN * HC];
__device__ int    g_cnt[NN];
__device__ int    g_off[NN];
__device__ int2   g_edge[NE];
__device__ float  g_scores[NN];

// ---------------- bf16 split helpers ----------------------------------------
__device__ __forceinline__ void split2(float x, float y, unsigned& h, unsigned& l) {
    __nv_bfloat162 hh = __floats2bfloat162_rn(x, y);
    float hx = __bfloat162float(hh.x), hy = __bfloat162float(hh.y);
    __nv_bfloat162 ll = __floats2bfloat162_rn(x - hx, y - hy);
    h = *reinterpret_cast<unsigned*>(&hh);
    l = *reinterpret_cast<unsigned*>(&ll);
}

#define MMA_BF16(d, a0, a1, a2, a3, b0, b1)                                    \
    asm volatile(                                                              \
        "mma.sync.aligned.m16n8k16.row.col.f32.bf16.bf16.f32 "                 \
        "{%0,%1,%2,%3}, {%4,%5,%6,%7}, {%8,%9}, {%0,%1,%2,%3};"                \
        : "+f"(d[0]), "+f"(d[1]), "+f"(d[2]), "+f"(d[3])                       \
        : "r"(a0), "r"(a1), "r"(a2), "r"(a3), "r"(b0), "r"(b1))

// ---------------- bf16-split HMMA GEMM (proven R10) --------------------------
#define PITCH 72
#define OFF_AH 0
#define OFF_AL (128 * PITCH * 2)
#define OFF_WH (2 * 128 * PITCH * 2)
#define OFF_WL (2 * 128 * PITCH * 2 + 192 * PITCH * 2)
#define SM_TOT (2 * 128 * PITCH * 2 + 2 * 192 * PITCH * 2)   // 92160 B

__global__ void __launch_bounds__(256) k_gemm_mma(
    const float* __restrict__ A,
    const float* __restrict__ Wl, const float* __restrict__ bl,
    const float* __restrict__ Wr, const float* __restrict__ br)
{
    extern __shared__ char sm[];
    __nv_bfloat16* AH = (__nv_bfloat16*)(sm + OFF_AH);
    __nv_bfloat16* AL = (__nv_bfloat16*)(sm + OFF_AL);
    __nv_bfloat16* WH = (__nv_bfloat16*)(sm + OFF_WH);
    __nv_bfloat16* WL = (__nv_bfloat16*)(sm + OFF_WL);

    int bz = blockIdx.y;
    const float* W    = bz ? Wr : Wl;
    const float* bias = bz ? br : bl;
    int row0 = blockIdx.x * 128;

    int tid  = threadIdx.x;
    int w    = tid >> 5;
    int lane = tid & 31;
    int g    = lane >> 2;
    int t    = lane & 3;
    int mw   = (w & 1) * 64;
    int nw   = (w >> 1) * 48;

    float acc[4][6][4];
    #pragma unroll
    for (int mf = 0; mf < 4; mf++)
        #pragma unroll
        for (int nf = 0; nf < 6; nf++)
            #pragma unroll
            for (int q = 0; q < 4; q++) acc[mf][nf][q] = 0.f;

    for (int kc = 0; kc < 2; kc++) {
        int k0f4 = kc * 16;
        __syncthreads();

        #pragma unroll
        for (int it = 0; it < 8; it++) {
            int idx = it * 256 + tid;
            int row = idx >> 4;
            int fq  = idx & 15;
            int gr  = row0 + row;
            if (gr >= NN) gr = NN - 1;
            float4 v = ((const float4*)A)[(size_t)gr * 32 + k0f4 + fq];
            unsigned h01, l01, h23, l23;
            split2(v.x, v.y, h01, l01);
            split2(v.z, v.w, h23, l23);
            int e = row * PITCH + fq * 4;
            *(uint2*)&AH[e] = make_uint2(h01, h23);
            *(uint2*)&AL[e] = make_uint2(l01, l23);
        }
        #pragma unroll
        for (int it = 0; it < 12; it++) {
            int idx = it * 256 + tid;
            int row = idx >> 4;
            int fq  = idx & 15;
            float4 v = ((const float4*)W)[(size_t)row * 32 + k0f4 + fq];
            unsigned h01, l01, h23, l23;
            split2(v.x, v.y, h01, l01);
            split2(v.z, v.w, h23, l23);
            int e = row * PITCH + fq * 4;
            *(uint2*)&WH[e] = make_uint2(h01, h23);
            *(uint2*)&WL[e] = make_uint2(l01, l23);
        }
        __syncthreads();

        #pragma unroll
        for (int ks = 0; ks < 4; ks++) {
            int kk = ks * 16;
            unsigned ah[4][4], al[4][4], bh[6][2], blo[6][2];
            #pragma unroll
            for (int mf = 0; mf < 4; mf++) {
                int r = mw + mf * 16 + g;
                int e0 = r * PITCH + kk + 2 * t;
                int e1 = (r + 8) * PITCH + kk + 2 * t;
                ah[mf][0] = *(const unsigned*)&AH[e0];
                ah[mf][1] = *(const unsigned*)&AH[e1];
                ah[mf][2] = *(const unsigned*)&AH[e0 + 8];
                ah[mf][3] = *(const unsigned*)&AH[e1 + 8];
                al[mf][0] = *(const unsigned*)&AL[e0];
                al[mf][1] = *(const unsigned*)&AL[e1];
                al[mf][2] = *(const unsigned*)&AL[e0 + 8];
                al[mf][3] = *(const unsigned*)&AL[e1 + 8];
            }
            #pragma unroll
            for (int nf = 0; nf < 6; nf++) {
                int c = nw + nf * 8 + g;
                int e = c * PITCH + kk + 2 * t;
                bh[nf][0]  = *(const unsigned*)&WH[e];
                bh[nf][1]  = *(const unsigned*)&WH[e + 8];
                blo[nf][0] = *(const unsigned*)&WL[e];
                blo[nf][1] = *(const unsigned*)&WL[e + 8];
            }
            #pragma unroll
            for (int mf = 0; mf < 4; mf++)
                #pragma unroll
                for (int nf = 0; nf < 6; nf++) {
                    MMA_BF16(acc[mf][nf], ah[mf][0], ah[mf][1], ah[mf][2], ah[mf][3],
                             bh[nf][0], bh[nf][1]);
                    MMA_BF16(acc[mf][nf], ah[mf][0], ah[mf][1], ah[mf][2], ah[mf][3],
                             blo[nf][0], blo[nf][1]);
                    MMA_BF16(acc[mf][nf], al[mf][0], al[mf][1], al[mf][2], al[mf][3],
                             bh[nf][0], bh[nf][1]);
                }
        }
    }

    #pragma unroll
    for (int mf = 0; mf < 4; mf++) {
        int r0 = row0 + mw + mf * 16 + g;
        #pragma unroll
        for (int nf = 0; nf < 6; nf++) {
            int col = nw + nf * 8 + 2 * t;
            float b0 = __ldg(&bias[col]), b1 = __ldg(&bias[col + 1]);
            float* d = acc[mf][nf];
            if (bz) {
                if (r0 < NN)
                    *(float2*)&g_xr[(size_t)r0 * HC + col] = make_float2(d[0] + b0, d[1] + b1);
                if (r0 + 8 < NN)
                    *(float2*)&g_xr[(size_t)(r0 + 8) * HC + col] = make_float2(d[2] + b0, d[3] + b1);
            } else {
                if (r0 < NN)
                    *(__half2*)&g_xlh[(size_t)r0 * HC + col] = __floats2half2_rn(d[0] + b0, d[1] + b1);
                if (r0 + 8 < NN)
                    *(__half2*)&g_xlh[(size_t)(r0 + 8) * HC + col] = __floats2half2_rn(d[2] + b0, d[3] + b1);
            }
        }
    }
}

// ---------------- histogram -------------------------------------------------
__global__ void k_hist(const int* __restrict__ ei) {
    int e = blockIdx.x * blockDim.x + threadIdx.x;
    if (e < NE) atomicAdd(&g_cnt[ei[NE + e]], 1);
}

// ---------------- x4-vectorized exclusive scan (single block) --------------
__global__ void k_scan() {
    __shared__ int wsum[32];
    __shared__ int carry;
    int tid  = threadIdx.x;
    int lane = tid & 31;
    int wid  = tid >> 5;
    if (tid == 0) carry = 0;
    __syncthreads();

    for (int base = 0; base < NN; base += 4096) {
        int idx = base + tid * 4;
        int4 v = make_int4(0, 0, 0, 0);
        if (idx < NN) v = *(const int4*)&g_cnt[idx];
        int t0 = v.x;
        int t1 = t0 + v.y;
        int t2 = t1 + v.z;
        int t3 = t2 + v.w;
        int x = t3;
        #pragma unroll
        for (int o = 1; o < 32; o <<= 1) {
            int t = __shfl_up_sync(0xffffffffu, x, o);
            if (lane >= o) x += t;
        }
        if (lane == 31) wsum[wid] = x;
        __syncthreads();
        if (wid == 0) {
            int s = wsum[lane];
            #pragma unroll
            for (int o = 1; o < 32; o <<= 1) {
                int t = __shfl_up_sync(0xffffffffu, s, o);
                if (lane >= o) s += t;
            }
            wsum[lane] = s;
        }
        __syncthreads();
        int c = carry;
        int b = (wid > 0 ? wsum[wid - 1] : 0) + c + x - t3;
        if (idx < NN)
            *(int4*)&g_off[idx] = make_int4(b, b + t0, b + t1, b + t2);
        __syncthreads();
        if (tid == 0) carry = c + wsum[31];
        __syncthreads();
    }
}

// ---------------- scatter ----------------------------------------------------
__global__ void k_scatter(const int* __restrict__ ei, const float* __restrict__ ea) {
    int e = blockIdx.x * blockDim.x + threadIdx.x;
    if (e >= NE) return;
    int s = ei[e];
    int d = ei[NE + e];
    int p = atomicAdd(&g_off[d], 1);
    g_edge[p] = make_int2(s, __float_as_int(ea[e]));
}

// ---------------- warp-per-node aggregation (R12 pipeline, fp16 gathers) ----
// lane (grp=l>>4, p=l&15) holds channels 64h + 4p..4p+3 per head h.
// edge recs fetched 2 iters ahead, xj gathers (fp16, 8B/head) 1 iter ahead.
__global__ void __launch_bounds__(128) k_agg(
    const float* __restrict__ We, const float* __restrict__ att,
    const float* __restrict__ bias, const float* __restrict__ Wout,
    const float* __restrict__ bout)
{
    int n = (blockIdx.x * blockDim.x + threadIdx.x) >> 5;
    int l = threadIdx.x & 31;
    if (n >= NN) return;
    int grp = l >> 4, p = l & 15;

    int end = g_off[n];
    int beg = (n > 0) ? g_off[n - 1] : 0;

    const float LOG2E = 1.44269504088896f;
    float4 xi[3], av[3], wv[3];
    {
        const float* xrp = &g_xr[(size_t)n * HC + 4 * p];
        #pragma unroll
        for (int h = 0; h < 3; h++) {
            xi[h] = *(const float4*)(xrp + 64 * h);
            float4 a = *(const float4*)&att[64 * h + 4 * p];
            av[h] = make_float4(a.x * LOG2E, a.y * LOG2E, a.z * LOG2E, a.w * LOG2E);
            wv[h] = *(const float4*)&We[64 * h + 4 * p];
        }
    }

    float  rsum[3] = {0.f, 0.f, 0.f};
    float4 acc[3]  = {{0,0,0,0}, {0,0,0,0}, {0,0,0,0}};

    if (end > beg) {
        int i0  = beg + grp;
        int lim = end - 1;
        int iA = (i0     < end) ? i0     : lim;
        int iB = (i0 + 2 < end) ? i0 + 2 : lim;
        int2 edA = g_edge[iA];
        int2 edB = g_edge[iB];
        uint2 ua0, ua1, ua2;                       // fp16x4 per head
        {
            const __half* bp = &g_xlh[(size_t)edA.x * HC + 4 * p];
            ua0 = *(const uint2*)(bp);
            ua1 = *(const uint2*)(bp + 64);
            ua2 = *(const uint2*)(bp + 128);
        }

        int niter = (end - beg + 1) >> 1;          // group-0 count (max)
        for (int it = 0; it < niter; it++) {
            int i = i0 + 2 * it;
            int iC = (i + 4 < end) ? i + 4 : lim;
            int2 edC = g_edge[iC];
            uint2 ub0, ub1, ub2;
            {
                const __half* bp = &g_xlh[(size_t)edB.x * HC + 4 * p];
                ub0 = *(const uint2*)(bp);
                ub1 = *(const uint2*)(bp + 64);
                ub2 = *(const uint2*)(bp + 128);
            }

            // convert current edge's fp16 -> fp32
            float2 c0 = __half22float2(*(__half2*)&ua0.x);
            float2 c1 = __half22float2(*(__half2*)&ua0.y);
            float4 xa0 = make_float4(c0.x, c0.y, c1.x, c1.y);
            c0 = __half22float2(*(__half2*)&ua1.x);
            c1 = __half22float2(*(__half2*)&ua1.y);
            float4 xa1 = make_float4(c0.x, c0.y, c1.x, c1.y);
            c0 = __half22float2(*(__half2*)&ua2.x);
            c1 = __half22float2(*(__half2*)&ua2.y);
            float4 xa2 = make_float4(c0.x, c0.y, c1.x, c1.y);

            float fe = __int_as_float(edA.y);
            float s0, s1, s2;
            {
                float mx, my, mz, mw_, sm, sa;
                // head 0
                mx  = fmaf(fe, wv[0].x, xi[0].x) + xa0.x;
                my  = fmaf(fe, wv[0].y, xi[0].y) + xa0.y;
                mz  = fmaf(fe, wv[0].z, xi[0].z) + xa0.z;
                mw_ = fmaf(fe, wv[0].w, xi[0].w) + xa0.w;
                sm = av[0].x * mx;               sa = av[0].x * fabsf(mx);
                sm = fmaf(av[0].y, my,  sm);     sa = fmaf(av[0].y, fabsf(my),  sa);
                sm = fmaf(av[0].z, mz,  sm);     sa = fmaf(av[0].z, fabsf(mz),  sa);
                sm = fmaf(av[0].w, mw_, sm);     sa = fmaf(av[0].w, fabsf(mw_), sa);
                s0 = fmaf(0.6f, sm, 0.4f * sa);
                // head 1
                mx  = fmaf(fe, wv[1].x, xi[1].x) + xa1.x;
                my  = fmaf(fe, wv[1].y, xi[1].y) + xa1.y;
                mz  = fmaf(fe, wv[1].z, xi[1].z) + xa1.z;
                mw_ = fmaf(fe, wv[1].w, xi[1].w) + xa1.w;
                sm = av[1].x * mx;               sa = av[1].x * fabsf(mx);
                sm = fmaf(av[1].y, my,  sm);     sa = fmaf(av[1].y, fabsf(my),  sa);
                sm = fmaf(av[1].z, mz,  sm);     sa = fmaf(av[1].z, fabsf(mz),  sa);
                sm = fmaf(av[1].w, mw_, sm);     sa = fmaf(av[1].w, fabsf(mw_), sa);
                s1 = fmaf(0.6f, sm, 0.4f * sa);
                // head 2
                mx  = fmaf(fe, wv[2].x, xi[2].x) + xa2.x;
                my  = fmaf(fe, wv[2].y, xi[2].y) + xa2.y;
                mz  = fmaf(fe, wv[2].z, xi[2].z) + xa2.z;
                mw_ = fmaf(fe, wv[2].w, xi[2].w) + xa2.w;
                sm = av[2].x * mx;               sa = av[2].x * fabsf(mx);
                sm = fmaf(av[2].y, my,  sm);     sa = fmaf(av[2].y, fabsf(my),  sa);
                sm = fmaf(av[2].z, mz,  sm);     sa = fmaf(av[2].z, fabsf(mz),  sa);
                sm = fmaf(av[2].w, mw_, sm);     sa = fmaf(av[2].w, fabsf(mw_), sa);
                s2 = fmaf(0.6f, sm, 0.4f * sa);
            }
            // 16-lane (within-group) reduction
            #pragma unroll
            for (int o = 8; o > 0; o >>= 1) {
                s0 += __shfl_xor_sync(0xffffffffu, s0, o);
                s1 += __shfl_xor_sync(0xffffffffu, s1, o);
                s2 += __shfl_xor_sync(0xffffffffu, s2, o);
            }
            bool valid = (i < end);
            float w0 = valid ? exp2f(s0) : 0.f;
            float w1 = valid ? exp2f(s1) : 0.f;
            float w2 = valid ? exp2f(s2) : 0.f;
            rsum[0] += w0; rsum[1] += w1; rsum[2] += w2;
            acc[0].x = fmaf(w0, xa0.x, acc[0].x); acc[0].y = fmaf(w0, xa0.y, acc[0].y);
            acc[0].z = fmaf(w0, xa0.z, acc[0].z); acc[0].w = fmaf(w0, xa0.w, acc[0].w);
            acc[1].x = fmaf(w1, xa1.x, acc[1].x); acc[1].y = fmaf(w1, xa1.y, acc[1].y);
            acc[1].z = fmaf(w1, xa1.z, acc[1].z); acc[1].w = fmaf(w1, xa1.w, acc[1].w);
            acc[2].x = fmaf(w2, xa2.x, acc[2].x); acc[2].y = fmaf(w2, xa2.y, acc[2].y);
            acc[2].z = fmaf(w2, xa2.z, acc[2].z); acc[2].w = fmaf(w2, xa2.w, acc[2].w);

            // rotate pipeline
            edA = edB; edB = edC;
            ua0 = ub0; ua1 = ub1; ua2 = ub2;
        }

        // combine the two groups (same channels at l and l^16)
        #pragma unroll
        for (int h = 0; h < 3; h++) {
            rsum[h] += __shfl_xor_sync(0xffffffffu, rsum[h], 16);
            acc[h].x += __shfl_xor_sync(0xffffffffu, acc[h].x, 16);
            acc[h].y += __shfl_xor_sync(0xffffffffu, acc[h].y, 16);
            acc[h].z += __shfl_xor_sync(0xffffffffu, acc[h].z, 16);
            acc[h].w += __shfl_xor_sync(0xffffffffu, acc[h].w, 16);
        }
    }

    float4 o = make_float4(0.f, 0.f, 0.f, 0.f);
    if (end > beg) {
        float r0 = 1.f / rsum[0], r1 = 1.f / rsum[1], r2 = 1.f / rsum[2];
        o.x = (acc[0].x * r0 + acc[1].x * r1 + acc[2].x * r2) * (1.f / 3.f);
        o.y = (acc[0].y * r0 + acc[1].y * r1 + acc[2].y * r2) * (1.f / 3.f);
        o.z = (acc[0].z * r0 + acc[1].z * r1 + acc[2].z * r2) * (1.f / 3.f);
        o.w = (acc[0].w * r0 + acc[1].w * r1 + acc[2].w * r2) * (1.f / 3.f);
    }
    float4 bia = *(const float4*)&bias[4 * p];
    float4 wo  = *(const float4*)&Wout[4 * p];
    o.x += bia.x; o.y += bia.y; o.z += bia.z; o.w += bia.w;

    float sp = o.x * wo.x + o.y * wo.y + o.z * wo.z + o.w * wo.w;
    #pragma unroll
    for (int off = 8; off > 0; off >>= 1)
        sp += __shfl_xor_sync(0xffffffffu, sp, off);
    if (l == 0) g_scores[n] = sp + bout[0];
}

// ---------------- global softmax over 50k scores ---------------------------
__global__ void k_softmax(float* __restrict__ out) {
    __shared__ float redm[32];
    __shared__ float reds[32];
    int tid = threadIdx.x;

    float mx = -1e30f;
    for (int i = tid; i < NN; i += 1024) mx = fmaxf(mx, g_scores[i]);
    #pragma unroll
    for (int o = 16; o > 0; o >>= 1) mx = fmaxf(mx, __shfl_xor_sync(0xffffffffu, mx, o));
    if ((tid & 31) == 0) redm[tid >> 5] = mx;
    __syncthreads();
    if (tid < 32) {
        float v = redm[tid];
        #pragma unroll
        for (int o = 16; o > 0; o >>= 1) v = fmaxf(v, __shfl_xor_sync(0xffffffffu, v, o));
        redm[tid] = v;
    }
    __syncthreads();
    mx = redm[0];

    float sm = 0.f;
    for (int i = tid; i < NN; i += 1024) {
        float e = __expf(g_scores[i] - mx);
        out[i] = e;
        sm += e;
    }
    #pragma unroll
    for (int o = 16; o > 0; o >>= 1) sm += __shfl_xor_sync(0xffffffffu, sm, o);
    if ((tid & 31) == 0) reds[tid >> 5] = sm;
    __syncthreads();
    if (tid < 32) {
        float v = reds[tid];
        #pragma unroll
        for (int o = 16; o > 0; o >>= 1) v += __shfl_xor_sync(0xffffffffu, v, o);
        reds[tid] = v;
    }
    __syncthreads();
    float inv = 1.f / reds[0];

    for (int i = tid; i < NN; i += 1024) out[i] *= inv;
}

// ---------------- launch: fork CSR-build chain || HMMA GEMM ----------------
extern "C" void kernel_launch(void* const* d_in, const int* in_sizes, int n_in,
                              void* d_out, int out_size)
{
    const int*   ei   = (const int*)  d_in[0];
    const float* ea   = (const float*)d_in[1];
    const float* pe   = (const float*)d_in[2];
    // d_in[3] = sim_w: softmax over one element == 1.0 -> unused
    const float* Wl   = (const float*)d_in[4];
    const float* bl   = (const float*)d_in[5];
    const float* Wr   = (const float*)d_in[6];
    const float* br   = (const float*)d_in[7];
    const float* We   = (const float*)d_in[8];
    const float* att  = (const float*)d_in[9];
    const float* bgn  = (const float*)d_in[10];
    const float* Wout = (const float*)d_in[11];
    const float* bout = (const float*)d_in[12];
    float* out = (float*)d_out;

    static cudaStream_t s1 = nullptr;
    static cudaEvent_t evr = nullptr, evg = nullptr;
    if (s1 == nullptr) {
        cudaStreamCreateWithFlags(&s1, cudaStreamNonBlocking);
        cudaEventCreateWithFlags(&evr, cudaEventDisableTiming);
        cudaEventCreateWithFlags(&evg, cudaEventDisableTiming);
        cudaFuncSetAttribute(k_gemm_mma, cudaFuncAttributeMaxDynamicSharedMemorySize, SM_TOT);
    }

    void* p_cnt = nullptr;
    cudaGetSymbolAddress(&p_cnt, g_cnt);

    // fork: GEMM on s1, CSR build on default stream
    cudaEventRecord(evr, 0);
    cudaStreamWaitEvent(s1, evr, 0);
    k_gemm_mma<<<dim3(GEMM_BX, 2), 256, SM_TOT, s1>>>(pe, Wl, bl, Wr, br);
    cudaEventRecord(evg, s1);

    cudaMemsetAsync(p_cnt, 0, NN * sizeof(int), 0);
    k_hist<<<HIST_BLOCKS, 256>>>(ei);
    k_scan<<<1, 1024>>>();
    k_scatter<<<HIST_BLOCKS, 256>>>(ei, ea);

    // join: aggregation needs both xl/xr and the CSR
    cudaStreamWaitEvent(0, evg, 0);
    k_agg<<<(NN * 32 + 127) / 128, 128>>>(We, att, bgn, Wout, bout);
    k_softmax<<<1, 1024>>>(out);
}